// round 6
// baseline (speedup 1.0000x reference)
#include <cuda_runtime.h>
#include <stdint.h>

#define NMAX 100000
#define EMAX 1250000
#define SCAN_CHUNK 512
#define NBMAX 256   // ceil(NMAX/SCAN_CHUNK) = 196 <= 256

// ---- scratch: __device__ globals, referenced ONLY inside device code ----
__device__ __align__(16) float g_y1[(size_t)NMAX * 128];  // [a1 | r1]
__device__ __align__(16) float g_h [(size_t)NMAX * 64];   // hidden after relu
__device__ __align__(16) float g_y2[(size_t)NMAX * 80];   // [a2 | r2]
__device__ int g_cnt[NMAX];      // in-degree
__device__ int g_rowptr[NMAX];   // CSR row start
__device__ int g_cursor[NMAX];   // fill cursor
__device__ int g_adj[EMAX];      // CSR column (src node) array
__device__ int g_part[NBMAX];    // scan partials
__device__ int g_is64;           // 1 if edge_index is int64, 0 if int32

// ---------------------------------------------------------------------------
// edge-index loader: pos in [0, 2E); dispatches on detected dtype, clamps.
__device__ __forceinline__ int load_idx(const void* ei, long long pos, int n) {
    long long v;
    if (g_is64) v = ((const long long*)ei)[pos];
    else        v = (long long)((const int*)ei)[pos];
    if (v < 0) v = 0;
    if (v >= n) v = n - 1;
    return (int)v;
}

// 0. dtype detection: int64 little-endian values < 2^31 => odd 32-bit words all 0
__global__ void k_detect(const int* __restrict__ ei32, long long nwords) {
    __shared__ int any_nz;
    if (threadIdx.x == 0) any_nz = 0;
    __syncthreads();
    long long lim = nwords < 32768 ? nwords : 32768;
    for (long long i = 1 + 2 * (long long)threadIdx.x; i < lim; i += 2 * blockDim.x)
        if (ei32[i] != 0) { any_nz = 1; break; }
    __syncthreads();
    if (threadIdx.x == 0) g_is64 = (any_nz == 0) ? 1 : 0;
}

// 1. zero degree counters
__global__ void k_zero_cnt(int n) {
    int i = blockIdx.x * blockDim.x + threadIdx.x;
    if (i < n) g_cnt[i] = 0;
}

// 2. in-degree histogram (scalar int atomics)
__global__ void k_deg(const void* __restrict__ ei, int n_edges, int n) {
    int e = blockIdx.x * blockDim.x + threadIdx.x;
    if (e >= n_edges) return;
    int dst = load_idx(ei, (long long)n_edges + e, n);
    atomicAdd(&g_cnt[dst], 1);
}

// 3a. per-chunk sums
__global__ void k_scan1(int n) {
    __shared__ int sh[SCAN_CHUNK];
    int i = blockIdx.x * SCAN_CHUNK + threadIdx.x;
    sh[threadIdx.x] = (i < n) ? g_cnt[i] : 0;
    __syncthreads();
    for (int off = SCAN_CHUNK / 2; off > 0; off >>= 1) {
        if (threadIdx.x < off) sh[threadIdx.x] += sh[threadIdx.x + off];
        __syncthreads();
    }
    if (threadIdx.x == 0) g_part[blockIdx.x] = sh[0];
}

// 3b. exclusive scan of chunk sums (one block)
__global__ void k_scan2(int nb) {
    __shared__ int sh[NBMAX];
    int t = threadIdx.x;
    int v = (t < nb) ? g_part[t] : 0;
    sh[t] = v;
    __syncthreads();
    for (int off = 1; off < NBMAX; off <<= 1) {
        int u = (t >= off) ? sh[t - off] : 0;
        __syncthreads();
        sh[t] += u;
        __syncthreads();
    }
    if (t < nb) g_part[t] = sh[t] - v;   // exclusive
}

// 3c. per-chunk exclusive scan + chunk offset -> rowptr, cursor
__global__ void k_scan3(int n) {
    __shared__ int sh[SCAN_CHUNK];
    int t = threadIdx.x;
    int i = blockIdx.x * SCAN_CHUNK + t;
    int v = (i < n) ? g_cnt[i] : 0;
    sh[t] = v;
    __syncthreads();
    for (int off = 1; off < SCAN_CHUNK; off <<= 1) {
        int u = (t >= off) ? sh[t - off] : 0;
        __syncthreads();
        sh[t] += u;
        __syncthreads();
    }
    if (i < n) {
        int start = g_part[blockIdx.x] + sh[t] - v;
        g_rowptr[i] = start;
        g_cursor[i] = start;
    }
}

// 4. fill adjacency
__global__ void k_fill(const void* __restrict__ ei, int n_edges, int n) {
    int e = blockIdx.x * blockDim.x + threadIdx.x;
    if (e >= n_edges) return;
    int src = load_idx(ei, e, n);
    int dst = load_idx(ei, (long long)n_edges + e, n);
    int pos = atomicAdd(&g_cursor[dst], 1);
    if (pos >= 0 && pos < EMAX) g_adj[pos] = src;
}

// ---------------------------------------------------------------------------
// fused GEMM body: Y[n][OUT] = X[n][64] @ [Wl | Wr]
template <int OUT>
__device__ __forceinline__ void gemm_body(const float* __restrict__ X,
                                          const float* __restrict__ Wl,
                                          const float* __restrict__ Wr,
                                          float* __restrict__ Y, int n) {
    constexpr int OUTL = OUT / 2;
    constexpr int NI = (OUT + 31) / 32;
    __shared__ float Ws[64 * OUT];
    __shared__ float xs[32 * 64];

    for (int i = threadIdx.x; i < 64 * OUTL; i += 256) {
        int k = i / OUTL, j = i - k * OUTL;
        Ws[k * OUT + j]        = Wl[i];
        Ws[k * OUT + OUTL + j] = Wr[i];
    }
    int base = blockIdx.x * 32;
    for (int i = threadIdx.x; i < 32 * 64; i += 256) {
        int node = base + (i >> 6);
        xs[i] = (node < n) ? X[(long long)node * 64 + (i & 63)] : 0.f;
    }
    __syncthreads();

    int wid = threadIdx.x >> 5, lane = threadIdx.x & 31;
    float acc[4][NI];
#pragma unroll
    for (int m = 0; m < 4; m++)
#pragma unroll
        for (int i = 0; i < NI; i++) acc[m][i] = 0.f;

#pragma unroll 8
    for (int k = 0; k < 64; k++) {
        float xv0 = xs[(wid * 4 + 0) * 64 + k];
        float xv1 = xs[(wid * 4 + 1) * 64 + k];
        float xv2 = xs[(wid * 4 + 2) * 64 + k];
        float xv3 = xs[(wid * 4 + 3) * 64 + k];
#pragma unroll
        for (int i = 0; i < NI; i++) {
            int j = lane + 32 * i;
            float w = (j < OUT) ? Ws[k * OUT + j] : 0.f;
            acc[0][i] += xv0 * w;
            acc[1][i] += xv1 * w;
            acc[2][i] += xv2 * w;
            acc[3][i] += xv3 * w;
        }
    }
#pragma unroll
    for (int m = 0; m < 4; m++) {
        int node = base + wid * 4 + m;
        if (node < n) {
#pragma unroll
            for (int i = 0; i < NI; i++) {
                int j = lane + 32 * i;
                if (j < OUT) Y[(long long)node * OUT + j] = acc[m][i];
            }
        }
    }
}

// 5. y1 = x @ [W1_l | W1_r]
__global__ __launch_bounds__(256) void k_gemm1(const float* __restrict__ X,
                                               const float* __restrict__ Wl,
                                               const float* __restrict__ Wr, int n) {
    gemm_body<128>(X, Wl, Wr, g_y1, n);
}

// 7. y2 = h @ [W2_l | W2_r]
__global__ __launch_bounds__(256) void k_gemm2(const float* __restrict__ Wl,
                                               const float* __restrict__ Wr, int n) {
    gemm_body<80>(g_h, Wl, Wr, g_y2, n);
}

// ---------------------------------------------------------------------------
// 6. layer-1 aggregation (gather) + mean + bias + root + relu -> g_h
__global__ __launch_bounds__(256) void k_agg1(const float* __restrict__ b1, int n) {
    int node = blockIdx.x * 8 + (threadIdx.x >> 5);
    int lane = threadIdx.x & 31;
    if (node >= n) return;
    int start = g_rowptr[node];
    int cnt = g_cnt[node];
    float a0 = 0.f, a1 = 0.f;
    for (int j = 0; j < cnt; j++) {
        int src = g_adj[start + j];
        const float* row = g_y1 + (long long)src * 128;
        a0 += row[lane];
        a1 += row[lane + 32];
    }
    float invd = 1.f / fmaxf((float)cnt, 1.f);
    const float* my = g_y1 + (long long)node * 128 + 64;
    float h0 = fmaxf(fmaf(a0, invd, b1[lane]      + my[lane]),      0.f);
    float h1 = fmaxf(fmaf(a1, invd, b1[lane + 32] + my[lane + 32]), 0.f);
    float* out = g_h + (long long)node * 64;
    out[lane] = h0;
    out[lane + 32] = h1;
}

// 8. layer-2 aggregation + mean + bias + root + log_softmax -> d_out
__global__ __launch_bounds__(256) void k_agg2(const float* __restrict__ b2,
                                              float* __restrict__ out, int n) {
    int node = blockIdx.x * 8 + (threadIdx.x >> 5);
    int lane = threadIdx.x & 31;
    if (node >= n) return;
    int start = g_rowptr[node];
    int cnt = g_cnt[node];
    float a0 = 0.f, a1 = 0.f;
    for (int j = 0; j < cnt; j++) {
        int src = g_adj[start + j];
        const float* row = g_y2 + (long long)src * 80;
        a0 += row[lane];
        if (lane < 8) a1 += row[lane + 32];
    }
    float invd = 1.f / fmaxf((float)cnt, 1.f);
    const float* my = g_y2 + (long long)node * 80 + 40;
    float v0 = fmaf(a0, invd, b2[lane] + my[lane]);
    float v1 = __int_as_float(0xff800000);  // -inf
    if (lane < 8) v1 = fmaf(a1, invd, b2[lane + 32] + my[lane + 32]);
    float m = fmaxf(v0, v1);
#pragma unroll
    for (int o = 16; o > 0; o >>= 1) m = fmaxf(m, __shfl_xor_sync(0xffffffffu, m, o));
    float s = expf(v0 - m) + ((lane < 8) ? expf(v1 - m) : 0.f);
#pragma unroll
    for (int o = 16; o > 0; o >>= 1) s += __shfl_xor_sync(0xffffffffu, s, o);
    float ls = m + logf(s);
    out[(long long)node * 40 + lane] = v0 - ls;
    if (lane < 8) out[(long long)node * 40 + lane + 32] = v1 - ls;
}

// ---------------------------------------------------------------------------
extern "C" void kernel_launch(void* const* d_in, const int* in_sizes, int n_in,
                              void* d_out, int out_size) {
    const float* x   = (const float*)d_in[0];
    const void*  ei  = d_in[1];
    const float* W1l = (const float*)d_in[2];
    const float* b1  = (const float*)d_in[3];
    const float* W1r = (const float*)d_in[4];
    const float* W2l = (const float*)d_in[5];
    const float* b2  = (const float*)d_in[6];
    const float* W2r = (const float*)d_in[7];
    float* out = (float*)d_out;

    int n = in_sizes[0] / 64;
    int E = in_sizes[1] / 2;
    int nb = (n + SCAN_CHUNK - 1) / SCAN_CHUNK;

    // 0. edge dtype detection (int32 vs int64)
    k_detect<<<1, 256>>>((const int*)ei, (long long)2 * E);

    // CSR build
    k_zero_cnt<<<(n + 255) / 256, 256>>>(n);
    k_deg<<<(E + 255) / 256, 256>>>(ei, E, n);
    k_scan1<<<nb, SCAN_CHUNK>>>(n);
    k_scan2<<<1, NBMAX>>>(nb);
    k_scan3<<<nb, SCAN_CHUNK>>>(n);
    k_fill<<<(E + 255) / 256, 256>>>(ei, E, n);

    // layer 1
    k_gemm1<<<(n + 31) / 32, 256>>>(x, W1l, W1r, n);
    k_agg1<<<(n + 7) / 8, 256>>>(b1, n);

    // layer 2
    k_gemm2<<<(n + 31) / 32, 256>>>(W2l, W2r, n);
    k_agg2<<<(n + 7) / 8, 256>>>(b2, out, n);
}